// round 1
// baseline (speedup 1.0000x reference)
#include <cuda_runtime.h>
#include <cuda_bf16.h>

// ---------------------------------------------------------------------------
// IngredientPositionEncoding: segment-mean pooling over separator-delimited
// spans + sinusoidal positional encoding.
//
//   seg id of token = #separators strictly before it
//   segment s mean over non-separator tokens with seg==s (s < max_ingr)
//   out[b, s, :] = mean (or 0 if empty) + pe[s, :]
//
// Kernel 1: per batch row, find separator positions (block scan), emit
//           (flat_start, count) per segment into __device__ scratch.
// Kernel 2: per output row, stream the contiguous segment slab, mean, +pe.
// ---------------------------------------------------------------------------

#define MAX_SEPS_CAP 4096       // >= L in this problem; guard below
#define MAX_OUT_ROWS 65536      // >= B*max_ingr = 16384 here

__device__ int g_seg_start[MAX_OUT_ROWS];   // flat token index into x rows
__device__ int g_seg_cnt[MAX_OUT_ROWS];
__device__ int g_fallback_max_ingr = 256;   // used only if scalar input absent

// ---------------------------------------------------------------------------
// Kernel 1: segment boundaries. One block per batch row b (blocks with
// blockIdx.x >= B exit). 256 threads.
// ---------------------------------------------------------------------------
__global__ void __launch_bounds__(256)
seg_bounds_kernel(const int* __restrict__ mask,
                  const int* __restrict__ max_ingr_ptr,
                  int BL, int OUT_ROWS,
                  int* __restrict__ seg_start,
                  int* __restrict__ seg_cnt)
{
    const int max_ingr = *max_ingr_ptr;           // uniform broadcast load
    const int B = OUT_ROWS / max_ingr;
    const int L = BL / B;

    const int b = blockIdx.x;
    if (b >= B) return;

    __shared__ int sh_sep[MAX_SEPS_CAP];          // separator positions
    __shared__ int sh_cnt[256];
    __shared__ int sh_excl[257];

    const int* mrow = mask + (long long)b * L;
    const int tid = threadIdx.x;
    const int nthr = blockDim.x;
    const int chunk = (L + nthr - 1) / nthr;
    const int beg = tid * chunk;
    const int end = min(beg + chunk, L);

    // per-thread separator count
    int c = 0;
    for (int i = beg; i < end; ++i) c += (mrow[i] != 0);
    sh_cnt[tid] = c;
    __syncthreads();

    // exclusive scan (serial on thread 0 — 256 adds, negligible)
    if (tid == 0) {
        int acc = 0;
        for (int i = 0; i < nthr; ++i) { sh_excl[i] = acc; acc += sh_cnt[i]; }
        sh_excl[nthr] = acc;                      // total separators
    }
    __syncthreads();

    // scatter separator positions
    int j = sh_excl[tid];
    for (int i = beg; i < end; ++i) {
        if (mrow[i] != 0) {
            if (j < MAX_SEPS_CAP) sh_sep[j] = i;
            ++j;
        }
    }
    const int nsep = sh_excl[nthr];
    __syncthreads();

    // emit (start, cnt) per segment s in [0, max_ingr)
    for (int s = tid; s < max_ingr; s += nthr) {
        int start, cnt;
        if (s < nsep) {
            start = (s == 0) ? 0 : (sh_sep[s - 1] + 1);
            cnt   = sh_sep[s] - start;
        } else if (s == nsep) {
            // tokens after the last separator belong to segment nsep
            start = (nsep == 0) ? 0 : (sh_sep[nsep - 1] + 1);
            cnt   = L - start;
        } else {
            start = 0;
            cnt   = 0;
        }
        const int r = b * max_ingr + s;
        seg_start[r] = b * L + start;             // flat token index
        seg_cnt[r]   = cnt;
    }
}

// ---------------------------------------------------------------------------
// Kernel 2: segment means + positional encoding. One block per output row,
// D threads (thread = channel). Streams cnt contiguous rows of x.
// ---------------------------------------------------------------------------
__global__ void seg_mean_kernel(const float* __restrict__ x,
                                const float* __restrict__ pe,
                                const int* __restrict__ max_ingr_ptr,
                                const int* __restrict__ seg_start,
                                const int* __restrict__ seg_cnt,
                                float* __restrict__ out,
                                int D)
{
    const int r = blockIdx.x;
    const int d = threadIdx.x;
    if (d >= D) return;

    const int max_ingr = *max_ingr_ptr;
    const int s = r % max_ingr;

    const int start = seg_start[r];
    const int cnt   = seg_cnt[r];

    const float* __restrict__ xp = x + (long long)start * D + d;

    // 4-way unrolled independent accumulation for MLP
    float a0 = 0.f, a1 = 0.f, a2 = 0.f, a3 = 0.f;
    int t = 0;
    const long long stride = (long long)D;
    for (; t + 4 <= cnt; t += 4) {
        a0 += xp[(long long)(t + 0) * stride];
        a1 += xp[(long long)(t + 1) * stride];
        a2 += xp[(long long)(t + 2) * stride];
        a3 += xp[(long long)(t + 3) * stride];
    }
    for (; t < cnt; ++t) a0 += xp[(long long)t * stride];

    float sum = (a0 + a1) + (a2 + a3);
    float mean = (cnt > 0) ? (sum / (float)cnt) : 0.f;

    out[(long long)r * D + d] = mean + pe[(long long)s * D + d];
}

// ---------------------------------------------------------------------------
// Launch
// ---------------------------------------------------------------------------
extern "C" void kernel_launch(void* const* d_in, const int* in_sizes, int n_in,
                              void* d_out, int out_size)
{
    const float* x    = (const float*)d_in[0];
    const int*   mask = (const int*)d_in[1];
    const float* pe   = (const float*)d_in[2];

    const int* max_ingr_ptr;
    if (n_in >= 4) {
        max_ingr_ptr = (const int*)d_in[3];
    } else {
        int* p = nullptr;
        cudaGetSymbolAddress((void**)&p, g_fallback_max_ingr);
        max_ingr_ptr = p;
    }

    const int x_size    = in_sizes[0];            // B*L*D
    const int mask_size = in_sizes[1];            // B*L
    const int D         = x_size / mask_size;     // 128
    const int OUT_ROWS  = out_size / D;           // B*max_ingr = 16384

    int* seg_start_p = nullptr;
    int* seg_cnt_p   = nullptr;
    cudaGetSymbolAddress((void**)&seg_start_p, g_seg_start);
    cudaGetSymbolAddress((void**)&seg_cnt_p,   g_seg_cnt);

    // Kernel 1: one block per batch row; launch OUT_ROWS blocks, extras exit
    // immediately (B is only known on-device, B <= OUT_ROWS always).
    seg_bounds_kernel<<<OUT_ROWS, 256>>>(mask, max_ingr_ptr,
                                         mask_size, OUT_ROWS,
                                         seg_start_p, seg_cnt_p);

    // Kernel 2: one block per output row, D threads.
    seg_mean_kernel<<<OUT_ROWS, D>>>(x, pe, max_ingr_ptr,
                                     seg_start_p, seg_cnt_p,
                                     (float*)d_out, D);
}

// round 2
// speedup vs baseline: 1.2899x; 1.2899x over previous
#include <cuda_runtime.h>
#include <cuda_bf16.h>

// ---------------------------------------------------------------------------
// IngredientPositionEncoding: segment-mean pooling over separator-delimited
// spans + sinusoidal positional encoding.
//
// Kernel 1: per batch row, find separator positions (warp-shuffle scan), emit
//           (flat_start, count) per segment into __device__ scratch.
// Kernel 2: one WARP per output row; lane = float4 channel. Streams the
//           contiguous cnt x D slab with 16B vector loads, 4-deep unroll.
// ---------------------------------------------------------------------------

#define MAX_SEPS_CAP 4096       // >= L in this problem
#define MAX_OUT_ROWS 65536      // >= B*max_ingr

__device__ int g_seg_start[MAX_OUT_ROWS];   // flat token index into x rows
__device__ int g_seg_cnt[MAX_OUT_ROWS];
__device__ int g_fallback_max_ingr = 256;

// ---------------------------------------------------------------------------
// Kernel 1: segment boundaries. One block per batch row b (extra blocks exit).
// ---------------------------------------------------------------------------
__global__ void __launch_bounds__(256)
seg_bounds_kernel(const int* __restrict__ mask,
                  const int* __restrict__ max_ingr_ptr,
                  int BL, int OUT_ROWS,
                  int* __restrict__ seg_start,
                  int* __restrict__ seg_cnt)
{
    const int max_ingr = *max_ingr_ptr;
    const int B = OUT_ROWS / max_ingr;
    const int L = BL / B;

    const int b = blockIdx.x;
    if (b >= B) return;

    __shared__ int sh_sep[MAX_SEPS_CAP];
    __shared__ int sh_warp[9];                 // 8 warp totals + grand total

    const int* mrow = mask + (long long)b * L;
    const int tid  = threadIdx.x;
    const int lane = tid & 31;
    const int wid  = tid >> 5;
    const int nthr = blockDim.x;
    const int chunk = (L + nthr - 1) / nthr;
    const int beg = tid * chunk;
    const int end = min(beg + chunk, L);

    // per-thread separator count
    int c = 0;
    for (int i = beg; i < end; ++i) c += (mrow[i] != 0);

    // warp inclusive scan
    int inc = c;
    #pragma unroll
    for (int o = 1; o < 32; o <<= 1) {
        int v = __shfl_up_sync(0xffffffffu, inc, o);
        if (lane >= o) inc += v;
    }
    if (lane == 31) sh_warp[wid] = inc;
    __syncthreads();

    // scan the 8 warp totals (serial, 8 adds)
    if (tid == 0) {
        int acc = 0;
        #pragma unroll
        for (int w = 0; w < 8; ++w) { int t = sh_warp[w]; sh_warp[w] = acc; acc += t; }
        sh_warp[8] = acc;                      // total separators
    }
    __syncthreads();

    const int excl = inc - c + sh_warp[wid];
    const int nsep = sh_warp[8];

    // scatter separator positions
    int j = excl;
    for (int i = beg; i < end; ++i) {
        if (mrow[i] != 0) {
            if (j < MAX_SEPS_CAP) sh_sep[j] = i;
            ++j;
        }
    }
    __syncthreads();

    // emit (start, cnt) per segment s in [0, max_ingr)
    for (int s = tid; s < max_ingr; s += nthr) {
        int start, cnt;
        if (s < nsep) {
            start = (s == 0) ? 0 : (sh_sep[s - 1] + 1);
            cnt   = sh_sep[s] - start;
        } else if (s == nsep) {
            start = (nsep == 0) ? 0 : (sh_sep[nsep - 1] + 1);
            cnt   = L - start;
        } else {
            start = 0;
            cnt   = 0;
        }
        const int r = b * max_ingr + s;
        seg_start[r] = b * L + start;
        seg_cnt[r]   = cnt;
    }
}

// ---------------------------------------------------------------------------
// Kernel 2 (fast path, D % 4 == 0): one warp per output row. Lane l owns
// float4 channels [4l, 4l+3] (looping if D/4 > 32). 16B vector loads,
// 4 independent accumulators -> 64B in flight per thread.
// ---------------------------------------------------------------------------
__global__ void __launch_bounds__(256)
seg_mean_v4_kernel(const float4* __restrict__ x4,
                   const float4* __restrict__ pe4,
                   const int* __restrict__ max_ingr_ptr,
                   const int* __restrict__ seg_start,
                   const int* __restrict__ seg_cnt,
                   float4* __restrict__ out4,
                   int D4, int OUT_ROWS)
{
    const int warps_per_block = blockDim.x >> 5;
    const int r = blockIdx.x * warps_per_block + (threadIdx.x >> 5);
    if (r >= OUT_ROWS) return;
    const int lane = threadIdx.x & 31;

    const int max_ingr = *max_ingr_ptr;
    const int s = r % max_ingr;

    const int start = seg_start[r];
    const int cnt   = seg_cnt[r];

    const float4* __restrict__ xp = x4 + (long long)start * D4;
    const float inv = (cnt > 0) ? (1.0f / (float)cnt) : 0.0f;

    for (int c = lane; c < D4; c += 32) {
        float4 a0 = {0.f,0.f,0.f,0.f}, a1 = a0, a2 = a0, a3 = a0;
        int t = 0;
        for (; t + 4 <= cnt; t += 4) {
            float4 v0 = xp[(long long)(t + 0) * D4 + c];
            float4 v1 = xp[(long long)(t + 1) * D4 + c];
            float4 v2 = xp[(long long)(t + 2) * D4 + c];
            float4 v3 = xp[(long long)(t + 3) * D4 + c];
            a0.x += v0.x; a0.y += v0.y; a0.z += v0.z; a0.w += v0.w;
            a1.x += v1.x; a1.y += v1.y; a1.z += v1.z; a1.w += v1.w;
            a2.x += v2.x; a2.y += v2.y; a2.z += v2.z; a2.w += v2.w;
            a3.x += v3.x; a3.y += v3.y; a3.z += v3.z; a3.w += v3.w;
        }
        for (; t < cnt; ++t) {
            float4 v = xp[(long long)t * D4 + c];
            a0.x += v.x; a0.y += v.y; a0.z += v.z; a0.w += v.w;
        }
        float4 sum;
        sum.x = (a0.x + a1.x) + (a2.x + a3.x);
        sum.y = (a0.y + a1.y) + (a2.y + a3.y);
        sum.z = (a0.z + a1.z) + (a2.z + a3.z);
        sum.w = (a0.w + a1.w) + (a2.w + a3.w);

        float4 p = pe4[(long long)s * D4 + c];
        float4 o;
        o.x = sum.x * inv + p.x;
        o.y = sum.y * inv + p.y;
        o.z = sum.z * inv + p.z;
        o.w = sum.w * inv + p.w;
        out4[(long long)r * D4 + c] = o;
    }
}

// ---------------------------------------------------------------------------
// Kernel 2 (generic fallback, any D): one block per row, thread = channel.
// ---------------------------------------------------------------------------
__global__ void seg_mean_scalar_kernel(const float* __restrict__ x,
                                       const float* __restrict__ pe,
                                       const int* __restrict__ max_ingr_ptr,
                                       const int* __restrict__ seg_start,
                                       const int* __restrict__ seg_cnt,
                                       float* __restrict__ out,
                                       int D)
{
    const int r = blockIdx.x;
    const int max_ingr = *max_ingr_ptr;
    const int s = r % max_ingr;
    const int start = seg_start[r];
    const int cnt   = seg_cnt[r];
    const float inv = (cnt > 0) ? (1.0f / (float)cnt) : 0.0f;

    for (int d = threadIdx.x; d < D; d += blockDim.x) {
        const float* xp = x + (long long)start * D + d;
        float a0 = 0.f, a1 = 0.f, a2 = 0.f, a3 = 0.f;
        int t = 0;
        for (; t + 4 <= cnt; t += 4) {
            a0 += xp[(long long)(t + 0) * D];
            a1 += xp[(long long)(t + 1) * D];
            a2 += xp[(long long)(t + 2) * D];
            a3 += xp[(long long)(t + 3) * D];
        }
        for (; t < cnt; ++t) a0 += xp[(long long)t * D];
        float sum = (a0 + a1) + (a2 + a3);
        out[(long long)r * D + d] = sum * inv + pe[(long long)s * D + d];
    }
}

// ---------------------------------------------------------------------------
// Launch
// ---------------------------------------------------------------------------
extern "C" void kernel_launch(void* const* d_in, const int* in_sizes, int n_in,
                              void* d_out, int out_size)
{
    const float* x    = (const float*)d_in[0];
    const int*   mask = (const int*)d_in[1];
    const float* pe   = (const float*)d_in[2];

    const int* max_ingr_ptr;
    if (n_in >= 4) {
        max_ingr_ptr = (const int*)d_in[3];
    } else {
        int* p = nullptr;
        cudaGetSymbolAddress((void**)&p, g_fallback_max_ingr);
        max_ingr_ptr = p;
    }

    const int x_size    = in_sizes[0];            // B*L*D
    const int mask_size = in_sizes[1];            // B*L
    const int D         = x_size / mask_size;     // 128
    const int OUT_ROWS  = out_size / D;           // B*max_ingr

    int* seg_start_p = nullptr;
    int* seg_cnt_p   = nullptr;
    cudaGetSymbolAddress((void**)&seg_start_p, g_seg_start);
    cudaGetSymbolAddress((void**)&seg_cnt_p,   g_seg_cnt);

    // Kernel 1: one block per batch row (extras exit on-device).
    seg_bounds_kernel<<<OUT_ROWS, 256>>>(mask, max_ingr_ptr,
                                         mask_size, OUT_ROWS,
                                         seg_start_p, seg_cnt_p);

    if ((D & 3) == 0) {
        const int D4 = D >> 2;
        const int warps_per_block = 8;            // 256 threads
        const int rows_per_block  = warps_per_block;
        const int grid = (OUT_ROWS + rows_per_block - 1) / rows_per_block;
        seg_mean_v4_kernel<<<grid, warps_per_block * 32>>>(
            (const float4*)x, (const float4*)pe, max_ingr_ptr,
            seg_start_p, seg_cnt_p, (float4*)d_out, D4, OUT_ROWS);
    } else {
        seg_mean_scalar_kernel<<<OUT_ROWS, 128>>>(
            x, pe, max_ingr_ptr, seg_start_p, seg_cnt_p, (float*)d_out, D);
    }
}

// round 3
// speedup vs baseline: 1.6234x; 1.2585x over previous
#include <cuda_runtime.h>
#include <cuda_bf16.h>

// ---------------------------------------------------------------------------
// IngredientPositionEncoding: segment-mean pooling over separator-delimited
// spans + sinusoidal positional encoding.
//
// Kernel 1 (grid-stride over batch rows, 256 blocks): warp-shuffle scan of
//   the separator mask, emit packed int4 meta per output row:
//   (flat_start_token, count, segment_index, 0).
// Kernel 2 (block = 16 rows, 8 warps): metadata staged through shared once
//   per block; each warp streams 2 rows of contiguous tokens with float4
//   loads, 5-deep unroll (cnt=15 -> 3 iterations, no tail).
// ---------------------------------------------------------------------------

#define MAX_SEPS_CAP 4096       // >= L
#define MAX_OUT_ROWS 65536      // >= B*max_ingr
#define ROWS_PER_BLOCK 16

__device__ int4 g_seg_meta[MAX_OUT_ROWS];   // (flat_start, cnt, s, 0)
__device__ int  g_fallback_max_ingr = 256;

// ---------------------------------------------------------------------------
// Kernel 1: segment boundaries. Grid-stride over batch rows.
// ---------------------------------------------------------------------------
__global__ void __launch_bounds__(256)
seg_bounds_kernel(const int* __restrict__ mask,
                  const int* __restrict__ max_ingr_ptr,
                  int BL, int OUT_ROWS,
                  int4* __restrict__ meta)
{
    const int max_ingr = *max_ingr_ptr;
    const int B = OUT_ROWS / max_ingr;
    const int L = BL / B;

    __shared__ int sh_sep[MAX_SEPS_CAP];
    __shared__ int sh_warp[9];

    const int tid  = threadIdx.x;
    const int lane = tid & 31;
    const int wid  = tid >> 5;
    const int nthr = blockDim.x;

    for (int b = blockIdx.x; b < B; b += gridDim.x) {
        const int* mrow = mask + (long long)b * L;
        const int chunk = (L + nthr - 1) / nthr;
        const int beg = tid * chunk;
        const int end = min(beg + chunk, L);

        // per-thread separator count
        int c = 0;
        for (int i = beg; i < end; ++i) c += (mrow[i] != 0);

        // warp inclusive scan
        int inc = c;
        #pragma unroll
        for (int o = 1; o < 32; o <<= 1) {
            int v = __shfl_up_sync(0xffffffffu, inc, o);
            if (lane >= o) inc += v;
        }
        if (lane == 31) sh_warp[wid] = inc;
        __syncthreads();

        if (tid == 0) {
            int acc = 0;
            #pragma unroll
            for (int w = 0; w < 8; ++w) { int t = sh_warp[w]; sh_warp[w] = acc; acc += t; }
            sh_warp[8] = acc;
        }
        __syncthreads();

        const int excl = inc - c + sh_warp[wid];
        const int nsep = sh_warp[8];

        int j = excl;
        for (int i = beg; i < end; ++i) {
            if (mrow[i] != 0) {
                if (j < MAX_SEPS_CAP) sh_sep[j] = i;
                ++j;
            }
        }
        __syncthreads();

        for (int s = tid; s < max_ingr; s += nthr) {
            int start, cnt;
            if (s < nsep) {
                start = (s == 0) ? 0 : (sh_sep[s - 1] + 1);
                cnt   = sh_sep[s] - start;
            } else if (s == nsep) {
                start = (nsep == 0) ? 0 : (sh_sep[nsep - 1] + 1);
                cnt   = L - start;
            } else {
                start = 0;
                cnt   = 0;
            }
            int4 m;
            m.x = b * L + start;       // flat token index
            m.y = cnt;
            m.z = s;
            m.w = 0;
            meta[b * max_ingr + s] = m;
        }
        __syncthreads();               // protect sh_sep/sh_warp across b-iterations
    }
}

// ---------------------------------------------------------------------------
// Kernel 2 (fast path, D % 4 == 0): 256 threads = 8 warps per block, block
// owns ROWS_PER_BLOCK consecutive output rows; metadata staged via shared.
// ---------------------------------------------------------------------------
__global__ void __launch_bounds__(256)
seg_mean_v4_kernel(const float4* __restrict__ x4,
                   const float4* __restrict__ pe4,
                   const int4* __restrict__ meta,
                   float4* __restrict__ out4,
                   int D4, int OUT_ROWS)
{
    __shared__ int4 sh_meta[ROWS_PER_BLOCK];

    const int base = blockIdx.x * ROWS_PER_BLOCK;
    const int tid  = threadIdx.x;
    if (tid < ROWS_PER_BLOCK && base + tid < OUT_ROWS)
        sh_meta[tid] = meta[base + tid];
    __syncthreads();

    const int lane = tid & 31;
    const int w    = tid >> 5;

    for (int i = w; i < ROWS_PER_BLOCK; i += 8) {
        const int r = base + i;
        if (r >= OUT_ROWS) break;
        const int4 md  = sh_meta[i];
        const int start = md.x;
        const int cnt   = md.y;
        const int s     = md.z;

        const float4* __restrict__ xp = x4 + (long long)start * D4;
        const float inv = (cnt > 0) ? (1.0f / (float)cnt) : 0.0f;

        for (int c = lane; c < D4; c += 32) {
            float4 a0 = {0.f,0.f,0.f,0.f}, a1 = a0, a2 = a0, a3 = a0, a4 = a0;
            int t = 0;
            // 5-deep unroll: cnt=15 -> exactly 3 iterations, no tail
            for (; t + 5 <= cnt; t += 5) {
                float4 v0 = xp[(long long)(t + 0) * D4 + c];
                float4 v1 = xp[(long long)(t + 1) * D4 + c];
                float4 v2 = xp[(long long)(t + 2) * D4 + c];
                float4 v3 = xp[(long long)(t + 3) * D4 + c];
                float4 v4 = xp[(long long)(t + 4) * D4 + c];
                a0.x += v0.x; a0.y += v0.y; a0.z += v0.z; a0.w += v0.w;
                a1.x += v1.x; a1.y += v1.y; a1.z += v1.z; a1.w += v1.w;
                a2.x += v2.x; a2.y += v2.y; a2.z += v2.z; a2.w += v2.w;
                a3.x += v3.x; a3.y += v3.y; a3.z += v3.z; a3.w += v3.w;
                a4.x += v4.x; a4.y += v4.y; a4.z += v4.z; a4.w += v4.w;
            }
            for (; t < cnt; ++t) {
                float4 v = xp[(long long)t * D4 + c];
                a0.x += v.x; a0.y += v.y; a0.z += v.z; a0.w += v.w;
            }
            float4 sum;
            sum.x = ((a0.x + a1.x) + (a2.x + a3.x)) + a4.x;
            sum.y = ((a0.y + a1.y) + (a2.y + a3.y)) + a4.y;
            sum.z = ((a0.z + a1.z) + (a2.z + a3.z)) + a4.z;
            sum.w = ((a0.w + a1.w) + (a2.w + a3.w)) + a4.w;

            float4 p = pe4[(long long)s * D4 + c];
            float4 o;
            o.x = sum.x * inv + p.x;
            o.y = sum.y * inv + p.y;
            o.z = sum.z * inv + p.z;
            o.w = sum.w * inv + p.w;
            out4[(long long)r * D4 + c] = o;
        }
    }
}

// ---------------------------------------------------------------------------
// Kernel 2 (generic fallback, any D): one block per row, thread = channel.
// ---------------------------------------------------------------------------
__global__ void seg_mean_scalar_kernel(const float* __restrict__ x,
                                       const float* __restrict__ pe,
                                       const int4* __restrict__ meta,
                                       float* __restrict__ out,
                                       int D)
{
    const int r = blockIdx.x;
    const int4 md = meta[r];
    const int start = md.x;
    const int cnt   = md.y;
    const int s     = md.z;
    const float inv = (cnt > 0) ? (1.0f / (float)cnt) : 0.0f;

    for (int d = threadIdx.x; d < D; d += blockDim.x) {
        const float* xp = x + (long long)start * D + d;
        float a0 = 0.f, a1 = 0.f, a2 = 0.f, a3 = 0.f;
        int t = 0;
        for (; t + 4 <= cnt; t += 4) {
            a0 += xp[(long long)(t + 0) * D];
            a1 += xp[(long long)(t + 1) * D];
            a2 += xp[(long long)(t + 2) * D];
            a3 += xp[(long long)(t + 3) * D];
        }
        for (; t < cnt; ++t) a0 += xp[(long long)t * D];
        float sum = (a0 + a1) + (a2 + a3);
        out[(long long)r * D + d] = sum * inv + pe[(long long)s * D + d];
    }
}

// ---------------------------------------------------------------------------
// Launch
// ---------------------------------------------------------------------------
extern "C" void kernel_launch(void* const* d_in, const int* in_sizes, int n_in,
                              void* d_out, int out_size)
{
    const float* x    = (const float*)d_in[0];
    const int*   mask = (const int*)d_in[1];
    const float* pe   = (const float*)d_in[2];

    const int* max_ingr_ptr;
    if (n_in >= 4) {
        max_ingr_ptr = (const int*)d_in[3];
    } else {
        int* p = nullptr;
        cudaGetSymbolAddress((void**)&p, g_fallback_max_ingr);
        max_ingr_ptr = p;
    }

    const int x_size    = in_sizes[0];            // B*L*D
    const int mask_size = in_sizes[1];            // B*L
    const int D         = x_size / mask_size;     // 128
    const int OUT_ROWS  = out_size / D;           // B*max_ingr

    int4* meta_p = nullptr;
    cudaGetSymbolAddress((void**)&meta_p, g_seg_meta);

    // Kernel 1: grid-stride over batch rows (B resolved on-device).
    seg_bounds_kernel<<<256, 256>>>(mask, max_ingr_ptr,
                                    mask_size, OUT_ROWS, meta_p);

    if ((D & 3) == 0) {
        const int D4 = D >> 2;
        const int grid = (OUT_ROWS + ROWS_PER_BLOCK - 1) / ROWS_PER_BLOCK;
        seg_mean_v4_kernel<<<grid, 256>>>(
            (const float4*)x, (const float4*)pe, meta_p,
            (float4*)d_out, D4, OUT_ROWS);
    } else {
        seg_mean_scalar_kernel<<<OUT_ROWS, 128>>>(
            x, pe, meta_p, (float*)d_out, D);
    }
}

// round 4
// speedup vs baseline: 1.6250x; 1.0010x over previous
#include <cuda_runtime.h>
#include <cuda_bf16.h>

// ---------------------------------------------------------------------------
// IngredientPositionEncoding: segment-mean pooling over separator-delimited
// spans + sinusoidal positional encoding.
//
// Kernel 1 (grid-stride over batch rows): warp-shuffle scan of the separator
//   mask (int4 reads), emit packed int4 meta per output row:
//   (flat_start_token, count, segment_index, 0).
// Kernel 2 (block = 16 rows, 8 warps, TWO rows per warp): metadata staged
//   through shared; each warp streams both rows with float4 loads, batching
//   10 independent loads per iteration (160 B/thread MLP). cnt=15 -> 3
//   iterations, no tail.
// ---------------------------------------------------------------------------

#define MAX_SEPS_CAP 4096       // >= L
#define MAX_OUT_ROWS 65536      // >= B*max_ingr
#define ROWS_PER_BLOCK 16

__device__ int4 g_seg_meta[MAX_OUT_ROWS];   // (flat_start, cnt, s, 0)
__device__ int  g_fallback_max_ingr = 256;

// ---------------------------------------------------------------------------
// Kernel 1: segment boundaries. Grid-stride over batch rows.
// ---------------------------------------------------------------------------
__global__ void __launch_bounds__(256)
seg_bounds_kernel(const int* __restrict__ mask,
                  const int* __restrict__ max_ingr_ptr,
                  int BL, int OUT_ROWS,
                  int4* __restrict__ meta)
{
    const int max_ingr = *max_ingr_ptr;
    const int B = OUT_ROWS / max_ingr;
    const int L = BL / B;

    __shared__ int sh_sep[MAX_SEPS_CAP];
    __shared__ int sh_warp[9];

    const int tid  = threadIdx.x;
    const int lane = tid & 31;
    const int wid  = tid >> 5;
    const int nthr = blockDim.x;

    for (int b = blockIdx.x; b < B; b += gridDim.x) {
        const int* mrow = mask + (long long)b * L;
        const int chunk = (L + nthr - 1) / nthr;
        const int beg = tid * chunk;
        const int end = min(beg + chunk, L);

        // per-thread separator count (int4 fast path when aligned chunk of 4)
        int c = 0;
        if (((chunk & 3) == 0) && ((L & 3) == 0)) {
            const int4* m4 = (const int4*)(mrow + beg);
            const int n4 = (end - beg) >> 2;
            for (int i = 0; i < n4; ++i) {
                int4 v = m4[i];
                c += (v.x != 0) + (v.y != 0) + (v.z != 0) + (v.w != 0);
            }
        } else {
            for (int i = beg; i < end; ++i) c += (mrow[i] != 0);
        }

        // warp inclusive scan
        int inc = c;
        #pragma unroll
        for (int o = 1; o < 32; o <<= 1) {
            int v = __shfl_up_sync(0xffffffffu, inc, o);
            if (lane >= o) inc += v;
        }
        if (lane == 31) sh_warp[wid] = inc;
        __syncthreads();

        if (tid == 0) {
            int acc = 0;
            #pragma unroll
            for (int w = 0; w < 8; ++w) { int t = sh_warp[w]; sh_warp[w] = acc; acc += t; }
            sh_warp[8] = acc;
        }
        __syncthreads();

        const int excl = inc - c + sh_warp[wid];
        const int nsep = sh_warp[8];

        int j = excl;
        for (int i = beg; i < end; ++i) {
            if (mrow[i] != 0) {
                if (j < MAX_SEPS_CAP) sh_sep[j] = i;
                ++j;
            }
        }
        __syncthreads();

        for (int s = tid; s < max_ingr; s += nthr) {
            int start, cnt;
            if (s < nsep) {
                start = (s == 0) ? 0 : (sh_sep[s - 1] + 1);
                cnt   = sh_sep[s] - start;
            } else if (s == nsep) {
                start = (nsep == 0) ? 0 : (sh_sep[nsep - 1] + 1);
                cnt   = L - start;
            } else {
                start = 0;
                cnt   = 0;
            }
            int4 m;
            m.x = b * L + start;
            m.y = cnt;
            m.z = s;
            m.w = 0;
            meta[b * max_ingr + s] = m;
        }
        __syncthreads();
    }
}

// ---------------------------------------------------------------------------
// Kernel 2 (fast path, D % 4 == 0): 8 warps/block, each warp owns TWO
// consecutive output rows; 10 independent float4 loads batched per iteration.
// ---------------------------------------------------------------------------
__global__ void __launch_bounds__(256)
seg_mean_v4_kernel(const float4* __restrict__ x4,
                   const float4* __restrict__ pe4,
                   const int4* __restrict__ meta,
                   float4* __restrict__ out4,
                   int D4, int OUT_ROWS)
{
    __shared__ int4 sh_meta[ROWS_PER_BLOCK];

    const int base = blockIdx.x * ROWS_PER_BLOCK;
    const int tid  = threadIdx.x;
    if (tid < ROWS_PER_BLOCK && base + tid < OUT_ROWS)
        sh_meta[tid] = meta[base + tid];
    __syncthreads();

    const int lane = tid & 31;
    const int w    = tid >> 5;

    const int r0 = base + 2 * w;
    const int r1 = r0 + 1;
    if (r0 >= OUT_ROWS) return;
    const bool has1 = (r1 < OUT_ROWS);

    const int4 m0 = sh_meta[2 * w];
    const int4 m1 = has1 ? sh_meta[2 * w + 1] : make_int4(0, 0, 0, 0);

    const int start0 = m0.x, cnt0 = m0.y, s0 = m0.z;
    const int start1 = m1.x, cnt1 = m1.y, s1 = m1.z;

    const float4* __restrict__ p0 = x4 + (long long)start0 * D4;
    const float4* __restrict__ p1 = x4 + (long long)start1 * D4;
    const float inv0 = (cnt0 > 0) ? (1.0f / (float)cnt0) : 0.0f;
    const float inv1 = (cnt1 > 0) ? (1.0f / (float)cnt1) : 0.0f;
    const int mn = has1 ? min(cnt0, cnt1) : cnt0;

    for (int c = lane; c < D4; c += 32) {
        float4 a0 = {0.f, 0.f, 0.f, 0.f};
        float4 a1 = a0;
        int t = 0;
        // 5-deep per row, both rows batched: 10 independent loads in flight
        for (; t + 5 <= mn; t += 5) {
            float4 u0 = p0[(long long)(t + 0) * D4 + c];
            float4 u1 = p0[(long long)(t + 1) * D4 + c];
            float4 u2 = p0[(long long)(t + 2) * D4 + c];
            float4 u3 = p0[(long long)(t + 3) * D4 + c];
            float4 u4 = p0[(long long)(t + 4) * D4 + c];
            float4 v0 = p1[(long long)(t + 0) * D4 + c];
            float4 v1 = p1[(long long)(t + 1) * D4 + c];
            float4 v2 = p1[(long long)(t + 2) * D4 + c];
            float4 v3 = p1[(long long)(t + 3) * D4 + c];
            float4 v4 = p1[(long long)(t + 4) * D4 + c];
            a0.x += ((u0.x + u1.x) + (u2.x + u3.x)) + u4.x;
            a0.y += ((u0.y + u1.y) + (u2.y + u3.y)) + u4.y;
            a0.z += ((u0.z + u1.z) + (u2.z + u3.z)) + u4.z;
            a0.w += ((u0.w + u1.w) + (u2.w + u3.w)) + u4.w;
            a1.x += ((v0.x + v1.x) + (v2.x + v3.x)) + v4.x;
            a1.y += ((v0.y + v1.y) + (v2.y + v3.y)) + v4.y;
            a1.z += ((v0.z + v1.z) + (v2.z + v3.z)) + v4.z;
            a1.w += ((v0.w + v1.w) + (v2.w + v3.w)) + v4.w;
        }
        // tails (only run when counts differ or mn % 5 != 0)
        for (int t0 = t; t0 < cnt0; ++t0) {
            float4 u = p0[(long long)t0 * D4 + c];
            a0.x += u.x; a0.y += u.y; a0.z += u.z; a0.w += u.w;
        }
        if (has1) {
            for (int t1 = t; t1 < cnt1; ++t1) {
                float4 v = p1[(long long)t1 * D4 + c];
                a1.x += v.x; a1.y += v.y; a1.z += v.z; a1.w += v.w;
            }
        }

        float4 q0 = pe4[(long long)s0 * D4 + c];
        float4 o0;
        o0.x = a0.x * inv0 + q0.x;
        o0.y = a0.y * inv0 + q0.y;
        o0.z = a0.z * inv0 + q0.z;
        o0.w = a0.w * inv0 + q0.w;
        out4[(long long)r0 * D4 + c] = o0;

        if (has1) {
            float4 q1 = pe4[(long long)s1 * D4 + c];
            float4 o1;
            o1.x = a1.x * inv1 + q1.x;
            o1.y = a1.y * inv1 + q1.y;
            o1.z = a1.z * inv1 + q1.z;
            o1.w = a1.w * inv1 + q1.w;
            out4[(long long)r1 * D4 + c] = o1;
        }
    }
}

// ---------------------------------------------------------------------------
// Kernel 2 (generic fallback, any D): one block per row, thread = channel.
// ---------------------------------------------------------------------------
__global__ void seg_mean_scalar_kernel(const float* __restrict__ x,
                                       const float* __restrict__ pe,
                                       const int4* __restrict__ meta,
                                       float* __restrict__ out,
                                       int D)
{
    const int r = blockIdx.x;
    const int4 md = meta[r];
    const int start = md.x;
    const int cnt   = md.y;
    const int s     = md.z;
    const float inv = (cnt > 0) ? (1.0f / (float)cnt) : 0.0f;

    for (int d = threadIdx.x; d < D; d += blockDim.x) {
        const float* xp = x + (long long)start * D + d;
        float a0 = 0.f, a1 = 0.f, a2 = 0.f, a3 = 0.f;
        int t = 0;
        for (; t + 4 <= cnt; t += 4) {
            a0 += xp[(long long)(t + 0) * D];
            a1 += xp[(long long)(t + 1) * D];
            a2 += xp[(long long)(t + 2) * D];
            a3 += xp[(long long)(t + 3) * D];
        }
        for (; t < cnt; ++t) a0 += xp[(long long)t * D];
        float sum = (a0 + a1) + (a2 + a3);
        out[(long long)r * D + d] = sum * inv + pe[(long long)s * D + d];
    }
}

// ---------------------------------------------------------------------------
// Launch
// ---------------------------------------------------------------------------
extern "C" void kernel_launch(void* const* d_in, const int* in_sizes, int n_in,
                              void* d_out, int out_size)
{
    const float* x    = (const float*)d_in[0];
    const int*   mask = (const int*)d_in[1];
    const float* pe   = (const float*)d_in[2];

    const int* max_ingr_ptr;
    if (n_in >= 4) {
        max_ingr_ptr = (const int*)d_in[3];
    } else {
        int* p = nullptr;
        cudaGetSymbolAddress((void**)&p, g_fallback_max_ingr);
        max_ingr_ptr = p;
    }

    const int x_size    = in_sizes[0];            // B*L*D
    const int mask_size = in_sizes[1];            // B*L
    const int D         = x_size / mask_size;     // 128
    const int OUT_ROWS  = out_size / D;           // B*max_ingr

    int4* meta_p = nullptr;
    cudaGetSymbolAddress((void**)&meta_p, g_seg_meta);

    // Kernel 1: grid-stride over batch rows (B resolved on-device).
    seg_bounds_kernel<<<256, 256>>>(mask, max_ingr_ptr,
                                    mask_size, OUT_ROWS, meta_p);

    if ((D & 3) == 0) {
        const int D4 = D >> 2;
        const int grid = (OUT_ROWS + ROWS_PER_BLOCK - 1) / ROWS_PER_BLOCK;
        seg_mean_v4_kernel<<<grid, 256>>>(
            (const float4*)x, (const float4*)pe, meta_p,
            (float4*)d_out, D4, OUT_ROWS);
    } else {
        seg_mean_scalar_kernel<<<OUT_ROWS, 128>>>(
            x, pe, meta_p, (float*)d_out, D);
    }
}